// round 15
// baseline (speedup 1.0000x reference)
#include <cuda_runtime.h>

#define KW 7
#define PAD 3
#define H 480
#define W 640
#define NB 4
#define HW (H * W)
#define TX 32
#define TY 8
#define TILE_W (TX + 2 * PAD)   // 38
#define TILE_H (TY + 2 * PAD)   // 14
#define GX (W / TX)             // 20
#define GYT (H / TY)            // 60
#define NTILES (GX * GYT)       // 1200
#define NBLOCKS 1184            // 148 SMs x 8 blocks: exactly one wave
// exponent constant: -1/(2*0.1^2) * log2(e) = -50 * log2(e)
#define NEG50_LOG2E (-72.13475204444817f)

typedef unsigned long long u64;

__device__ __forceinline__ u64 pk(float lo, float hi) {
    u64 r; asm("mov.b64 %0, {%1, %2};" : "=l"(r) : "f"(lo), "f"(hi)); return r;
}
__device__ __forceinline__ void upk(float& lo, float& hi, u64 v) {
    asm("mov.b64 {%0, %1}, %2;" : "=f"(lo), "=f"(hi) : "l"(v));
}
__device__ __forceinline__ u64 add2(u64 a, u64 b) {
    u64 r; asm("add.rn.f32x2 %0, %1, %2;" : "=l"(r) : "l"(a), "l"(b)); return r;
}
__device__ __forceinline__ u64 mul2(u64 a, u64 b) {
    u64 r; asm("mul.rn.f32x2 %0, %1, %2;" : "=l"(r) : "l"(a), "l"(b)); return r;
}
__device__ __forceinline__ u64 fma2(u64 a, u64 b, u64 c) {
    u64 r; asm("fma.rn.f32x2 %0, %1, %2, %3;" : "=l"(r) : "l"(a), "l"(b), "l"(c)); return r;
}

// 2^e for a pair of f32 exponents via ONE MUFU op (ex2.approx.f16x2).
__device__ __forceinline__ u64 exp2pair(float e0, float e1) {
    u64 r;
    asm("{\n\t"
        ".reg .b32 p;\n\t"
        ".reg .b16 h0, h1;\n\t"
        ".reg .f32 f0, f1;\n\t"
        "cvt.rn.f16x2.f32 p, %2, %1;\n\t"   // p.hi = e1, p.lo = e0
        "ex2.approx.f16x2 p, p;\n\t"
        "mov.b32 {h0, h1}, p;\n\t"
        "cvt.f32.f16 f0, h0;\n\t"
        "cvt.f32.f16 f1, h1;\n\t"
        "mov.b64 %0, {f0, f1};\n\t"
        "}"
        : "=l"(r) : "f"(e0), "f"(e1));
    return r;
}

__global__ __launch_bounds__(TX * TY, 8) void bilateral_kernel(
    const float* __restrict__ I,
    const float* __restrict__ g,
    float* __restrict__ out)
{
    __shared__ ulonglong2 tile[TILE_H][TILE_W];   // batch-interleaved, 8512 B
    __shared__ float2 lg2s[KW * KW];              // pre-broadcast log2(g)

    const int tx = threadIdx.x;
    const int ty = threadIdx.y;
    const int tid = ty * TX + tx;

    if (tid < KW * KW) {
        const float lv = __log2f(__ldg(g + tid * HW));
        lg2s[tid] = make_float2(lv, lv);
    }

    // Fold-over grid: 1184 blocks cover 1200 tiles; blocks 0..15 do 2 tiles.
    for (int t = blockIdx.x; t < NTILES; t += NBLOCKS) {
        const int x0 = (t % GX) * TX;
        const int y0 = (t / GX) * TY;

        // Halo tile load (zero pad outside image), batch-interleaved.
        for (int i = tid; i < TILE_H * TILE_W; i += TX * TY) {
            const int ly = i / TILE_W;
            const int lx = i - ly * TILE_W;
            const int gy = y0 + ly - PAD;
            const int gx = x0 + lx - PAD;
            float4 v = make_float4(0.f, 0.f, 0.f, 0.f);
            if (gy >= 0 && gy < H && gx >= 0 && gx < W) {
                const int base = gy * W + gx;
                v.x = I[0 * HW + base];
                v.y = I[1 * HW + base];
                v.z = I[2 * HW + base];
                v.w = I[3 * HW + base];
            }
            *reinterpret_cast<float4*>(&tile[ly][lx]) = v;   // STS.128
        }
        __syncthreads();

        const ulonglong2 cc = tile[ty + PAD][tx + PAD];
        float c0, c1, c2, c3;
        upk(c0, c1, cc.x);
        upk(c2, c3, cc.y);
        const u64 nc01 = pk(-c0, -c1);
        const u64 nc23 = pk(-c2, -c3);
        const u64 C2 = pk(NEG50_LOG2E, NEG50_LOG2E);

        u64 num01 = 0ull, num23 = 0ull, den01 = 0ull, den23 = 0ull;

        #pragma unroll
        for (int dy = 0; dy < KW; dy++) {
            #pragma unroll
            for (int dx = 0; dx < KW; dx++) {
                const ulonglong2 s = tile[ty + dy][tx + dx];       // LDS.128
                const u64 lgb = *reinterpret_cast<const u64*>(&lg2s[dy * KW + dx]);

                const u64 d01 = add2(s.x, nc01);
                const u64 d23 = add2(s.y, nc23);
                const u64 q01 = mul2(d01, d01);
                const u64 q23 = mul2(d23, d23);
                const u64 e01 = fma2(C2, q01, lgb);
                const u64 e23 = fma2(C2, q23, lgb);

                float e0, e1, e2, e3;
                upk(e0, e1, e01);
                upk(e2, e3, e23);
                const u64 w01 = exp2pair(e0, e1);   // 1 MUFU for 2 exps
                const u64 w23 = exp2pair(e2, e3);

                den01 = add2(den01, w01);
                den23 = add2(den23, w23);
                num01 = fma2(w01, s.x, num01);
                num23 = fma2(w23, s.y, num23);
            }
        }

        float n0, n1, n2, n3, de0, de1, de2, de3;
        upk(n0, n1, num01); upk(n2, n3, num23);
        upk(de0, de1, den01); upk(de2, de3, den23);

        const int oidx = (y0 + ty) * W + (x0 + tx);
        out[0 * HW + oidx] = __fdividef(n0, de0);
        out[1 * HW + oidx] = __fdividef(n1, de1);
        out[2 * HW + oidx] = __fdividef(n2, de2);
        out[3 * HW + oidx] = __fdividef(n3, de3);

        __syncthreads();   // protect smem before next iteration's reload
    }
}

extern "C" void kernel_launch(void* const* d_in, const int* in_sizes, int n_in,
                              void* d_out, int out_size)
{
    const float* I = (const float*)d_in[0];
    const float* g = (const float*)d_in[1];
    float* out = (float*)d_out;

    dim3 block(TX, TY);
    bilateral_kernel<<<NBLOCKS, block>>>(I, g, out);
}